// round 16
// baseline (speedup 1.0000x reference)
#include <cuda_runtime.h>
#include <cuda_bf16.h>
#include <cstdint>

#define N_MAX 50000
#define E_MAX 640000
#define D 128
#define ROWLEN 129
#define EPSV 1e-9f
#define WMIN 1e-6f

// ---- static scratch ----
__device__ float g_norms[N_MAX];
__device__ float g_h[N_MAX];
__device__ float4 g_feat4[(size_t)N_MAX * 32];
__device__ int   g_deg[N_MAX];
__device__ int   g_cursor[N_MAX];
__device__ int   g_rowptr[N_MAX + 1];
__device__ int   g_col[E_MAX];
__device__ int   g_part[256];
__device__ unsigned short g_Ah[(size_t)N_MAX * 256];
__device__ unsigned short g_Al[(size_t)N_MAX * 256];
__device__ unsigned short g_Bh[128 * 256];
__device__ unsigned short g_Bl[128 * 256];

__device__ __forceinline__ void split_bf16(float v, unsigned short& h, unsigned short& l) {
    __nv_bfloat16 hb = __float2bfloat16(v);
    float lo = v - __bfloat162float(hb);
    h = __bfloat16_as_ushort(hb);
    l = __bfloat16_as_ushort(__float2bfloat16(lo));
}

__device__ __forceinline__ void mma_bf16(float* c, uint32_t a0, uint32_t a1, uint32_t a2, uint32_t a3,
                                         uint32_t b0, uint32_t b1) {
    asm volatile("mma.sync.aligned.m16n8k16.row.col.f32.bf16.bf16.f32 "
                 "{%0,%1,%2,%3}, {%4,%5,%6,%7}, {%8,%9}, {%0,%1,%2,%3};"
                 : "+f"(c[0]), "+f"(c[1]), "+f"(c[2]), "+f"(c[3])
                 : "r"(a0), "r"(a1), "r"(a2), "r"(a3), "r"(b0), "r"(b1));
}

#define KPAD 40

// Shared GEMM body: C[64,128] tile = A[:, kbase:kbase+128] @ B[:, kbase:kbase+128]^T.
// addIn=false: write raw (self term). addIn=true: add existing out, relu (final).
template<bool ADD>
__device__ __forceinline__ void gemm_tile(
    int gb, const float* __restrict__ x, float* __restrict__ out, int N, int kbase,
    unsigned short (*Ah)[KPAD], unsigned short (*Al)[KPAD],
    unsigned short (*Bh)[KPAD], unsigned short (*Bl)[KPAD])
{
    int t = threadIdx.x, lane = t & 31, wid = t >> 5;
    int row0 = gb * 64;
    int wr = (wid & 3) * 16;
    int wc = (wid >> 2) * 64;

    float acc[8][4];
#pragma unroll
    for (int i = 0; i < 8; i++)
#pragma unroll
        for (int j = 0; j < 4; j++) acc[i][j] = 0.f;

    for (int kk = 0; kk < 128; kk += 32) {
#pragma unroll
        for (int it = 0; it < 2; it++) {
            int p = t + it * 256;
            int row = p >> 3, u = p & 7;
            int r = row0 + row;
            uint2 vh = make_uint2(0u, 0u), vl = make_uint2(0u, 0u);
            if (r < N) {
                size_t src = (size_t)r * 256 + kbase + kk + u * 4;
                vh = *(const uint2*)(g_Ah + src);
                vl = *(const uint2*)(g_Al + src);
            }
            *(uint2*)&Ah[row][u * 4] = vh;
            *(uint2*)&Al[row][u * 4] = vl;
        }
#pragma unroll
        for (int it = 0; it < 4; it++) {
            int p = t + it * 256;
            int j = p >> 3, u = p & 7;
            size_t src = (size_t)j * 256 + kbase + kk + u * 4;
            *(uint2*)&Bh[j][u * 4] = *(const uint2*)(g_Bh + src);
            *(uint2*)&Bl[j][u * 4] = *(const uint2*)(g_Bl + src);
        }
        __syncthreads();
#pragma unroll
        for (int ks = 0; ks < 32; ks += 16) {
            int kq = ks + (lane & 3) * 2;
            int ra = wr + (lane >> 2);
            uint32_t ah0 = *(const uint32_t*)&Ah[ra][kq];
            uint32_t ah1 = *(const uint32_t*)&Ah[ra + 8][kq];
            uint32_t ah2 = *(const uint32_t*)&Ah[ra][kq + 8];
            uint32_t ah3 = *(const uint32_t*)&Ah[ra + 8][kq + 8];
            uint32_t al0 = *(const uint32_t*)&Al[ra][kq];
            uint32_t al1 = *(const uint32_t*)&Al[ra + 8][kq];
            uint32_t al2 = *(const uint32_t*)&Al[ra][kq + 8];
            uint32_t al3 = *(const uint32_t*)&Al[ra + 8][kq + 8];
#pragma unroll
            for (int nt = 0; nt < 8; nt++) {
                int cb = wc + nt * 8 + (lane >> 2);
                uint32_t bh0 = *(const uint32_t*)&Bh[cb][kq];
                uint32_t bh1 = *(const uint32_t*)&Bh[cb][kq + 8];
                uint32_t bl0 = *(const uint32_t*)&Bl[cb][kq];
                uint32_t bl1 = *(const uint32_t*)&Bl[cb][kq + 8];
                mma_bf16(acc[nt], ah0, ah1, ah2, ah3, bh0, bh1);
                mma_bf16(acc[nt], al0, al1, al2, al3, bh0, bh1);
                mma_bf16(acc[nt], ah0, ah1, ah2, ah3, bl0, bl1);
            }
        }
        __syncthreads();
    }

    int r1 = row0 + wr + (lane >> 2);
    int r2 = r1 + 8;
#pragma unroll
    for (int nt = 0; nt < 8; nt++) {
        int col = wc + nt * 8 + (lane & 3) * 2;
        if (r1 < N) {
            float* o = out + (size_t)r1 * ROWLEN + col;
            if (ADD) {
                o[0] = fmaxf(o[0] + acc[nt][0], 0.f);
                o[1] = fmaxf(o[1] + acc[nt][1], 0.f);
            } else {
                o[0] = acc[nt][0];
                o[1] = acc[nt][1];
            }
        }
        if (r2 < N) {
            float* o = out + (size_t)r2 * ROWLEN + col;
            if (ADD) {
                o[0] = fmaxf(o[0] + acc[nt][2], 0.f);
                o[1] = fmaxf(o[1] + acc[nt][3], 0.f);
            } else {
                o[0] = acc[nt][2];
                o[1] = acc[nt][3];
            }
        }
    }
    if (!ADD && t < 64) {
        int r = row0 + t;
        if (r < N) out[(size_t)r * ROWLEN + 128] = fmaxf(x[(size_t)r * ROWLEN + 128], 0.f);
    }
}

// ============================ fat kernel 1: hist + wconv + norms/feat-copy/feat-split ============================
__global__ void hist_wconv_norms_kernel(const int* __restrict__ ei, int E, int hBlocks,
                                        const float* __restrict__ Wn, const float* __restrict__ Ws,
                                        const float* __restrict__ x, int N) {
    int b = blockIdx.x;
    int t = threadIdx.x;
    if (b < hBlocks) {
        int e = b * 256 + t;
        if (e < E) atomicAdd(&g_deg[ei[e]], 1);
    } else if (b < hBlocks + 128) {
        int j = b - hBlocks;
        float v = (t < 128) ? Wn[j * 128 + t] : Ws[j * 128 + (t - 128)];
        split_bf16(v, g_Bh[j * 256 + t], g_Bl[j * 256 + t]);
    } else {
        int row = (b - hBlocks - 128) * 8 + (t >> 5);
        int lane = t & 31;
        if (row >= N) return;
        const float* xr = x + (size_t)row * ROWLEN;
        float a0 = xr[lane], a1 = xr[lane + 32], a2 = xr[lane + 64], a3 = xr[lane + 96];
        float* fr = (float*)(g_feat4 + (size_t)row * 32);
        fr[lane] = a0; fr[lane + 32] = a1; fr[lane + 64] = a2; fr[lane + 96] = a3;
        // feat-half bf16 split (A cols 128..255) — moved here from agg
        size_t base = (size_t)row * 256 + 128;
        split_bf16(a0, g_Ah[base + lane],      g_Al[base + lane]);
        split_bf16(a1, g_Ah[base + lane + 32], g_Al[base + lane + 32]);
        split_bf16(a2, g_Ah[base + lane + 64], g_Al[base + lane + 64]);
        split_bf16(a3, g_Ah[base + lane + 96], g_Al[base + lane + 96]);
        float s = a0 * a0 + a1 * a1 + a2 * a2 + a3 * a3;
#pragma unroll
        for (int off = 16; off > 0; off >>= 1) s += __shfl_xor_sync(0xffffffffu, s, off);
        if (lane == 0) {
            g_norms[row] = s + EPSV;
            g_h[row] = xr[128];
        }
    }
}

// ============================ scan ============================
__global__ void scan_part_kernel(int N) {
    __shared__ int ws[8];
    int t = threadIdx.x, b = blockIdx.x;
    int i = b * 256 + t;
    int v = (i < N) ? g_deg[i] : 0;
#pragma unroll
    for (int off = 16; off > 0; off >>= 1) v += __shfl_xor_sync(0xffffffffu, v, off);
    if ((t & 31) == 0) ws[t >> 5] = v;
    __syncthreads();
    if (t == 0) {
        int s = 0;
#pragma unroll
        for (int w = 0; w < 8; w++) s += ws[w];
        g_part[b] = s;
    }
}

__global__ void scan_final_kernel(int N, int nblk) {
    __shared__ int ws[8];
    __shared__ int boff;
    int t = threadIdx.x, b = blockIdx.x, lane = t & 31, w = t >> 5;

    int pv = (t < b && t < nblk) ? g_part[t] : 0;
#pragma unroll
    for (int off = 16; off > 0; off >>= 1) pv += __shfl_xor_sync(0xffffffffu, pv, off);
    if (lane == 0) ws[w] = pv;
    __syncthreads();
    if (t == 0) {
        int s = 0;
#pragma unroll
        for (int ww = 0; ww < 8; ww++) s += ws[ww];
        boff = s;
    }
    __syncthreads();
    int blockOff = boff;
    __syncthreads();

    int i = b * 256 + t;
    int v = (i < N) ? g_deg[i] : 0;
    int s = v;
#pragma unroll
    for (int off = 1; off < 32; off <<= 1) {
        int u = __shfl_up_sync(0xffffffffu, s, off);
        if (lane >= off) s += u;
    }
    if (lane == 31) ws[w] = s;
    __syncthreads();
    if (w == 0) {
        int p = (lane < 8) ? ws[lane] : 0;
#pragma unroll
        for (int off = 1; off < 8; off <<= 1) {
            int u = __shfl_up_sync(0xffffffffu, p, off);
            if (lane >= off) p += u;
        }
        if (lane < 8) ws[lane] = p;
    }
    __syncthreads();
    int incl = s + (w > 0 ? ws[w - 1] : 0);
    if (i < N) {
        g_rowptr[i + 1] = blockOff + incl;
        g_cursor[i]     = blockOff + incl - v;
    }
    if (b == 0 && t == 0) g_rowptr[0] = 0;
}

// ============================ fused scatter + feat-GEMM (self term) ============================
__global__ __launch_bounds__(256) void scatter_featgemm_kernel(
    const int* __restrict__ ei, int E, int hBlocks,
    const float* __restrict__ x, float* __restrict__ out, int N)
{
    __shared__ unsigned short Ah[64][KPAD], Al[64][KPAD];
    __shared__ unsigned short Bh[128][KPAD], Bl[128][KPAD];
    int b = blockIdx.x;
    if (b < hBlocks) {
        int e = b * 256 + threadIdx.x;
        if (e < E) {
            int r = ei[e];
            int c = ei[E + e];
            int pos = atomicAdd(&g_cursor[r], 1);
            g_col[pos] = c;
        }
        return;
    }
    // feat @ Ws^T  (A cols 128..255, B cols 128..255), raw write + homog col
    gemm_tile<false>(b - hBlocks, x, out, N, 128, Ah, Al, Bh, Bl);
}

// ============================ aggregation (neigh half only) ============================
__global__ void agg_kernel(int N) {
    int warp = (blockIdx.x * blockDim.x + threadIdx.x) >> 5;
    int lane = threadIdx.x & 31;
    if (warp >= N) return;
    int r = warp;
    float4 xrv = g_feat4[(size_t)r * 32 + lane];
    float xrh = g_h[r];
    float nr = g_norms[r];

    float4 acc = make_float4(0.f, 0.f, 0.f, 0.f);
    float wsum = 0.f;
    int jb = g_rowptr[r], je = g_rowptr[r + 1];
#pragma unroll 2
    for (int j = jb; j < je; j++) {
        int c = g_col[j];
        float nc = g_norms[c];
        float4 cv = g_feat4[(size_t)c * 32 + lane];
        float part = xrv.x * cv.x + xrv.y * cv.y + xrv.z * cv.z + xrv.w * cv.w;
        if (lane == 0) part = fmaf(xrh, g_h[c], part);
#pragma unroll
        for (int off = 16; off > 0; off >>= 1) part += __shfl_xor_sync(0xffffffffu, part, off);
        float w = __expf(part * part / (nr * nc) - 1.0f);
        acc.x = fmaf(w, cv.x, acc.x);
        acc.y = fmaf(w, cv.y, acc.y);
        acc.z = fmaf(w, cv.z, acc.z);
        acc.w = fmaf(w, cv.w, acc.w);
        wsum += w;
    }
    float inv = 1.0f / fmaxf(wsum, WMIN);
    unsigned short nh[4], nl[4];
    split_bf16(acc.x * inv, nh[0], nl[0]);
    split_bf16(acc.y * inv, nh[1], nl[1]);
    split_bf16(acc.z * inv, nh[2], nl[2]);
    split_bf16(acc.w * inv, nh[3], nl[3]);
    size_t base = (size_t)r * 256 + lane * 4;
    *(uint2*)(g_Ah + base) = *(const uint2*)nh;
    *(uint2*)(g_Al + base) = *(const uint2*)nl;
}

// ============================ final GEMM: neigh @ Wn^T + out, relu ============================
__global__ __launch_bounds__(256) void gemm_neigh_kernel(const float* __restrict__ x,
                                                         float* __restrict__ out, int N)
{
    __shared__ unsigned short Ah[64][KPAD], Al[64][KPAD];
    __shared__ unsigned short Bh[128][KPAD], Bl[128][KPAD];
    gemm_tile<true>(blockIdx.x, x, out, N, 0, Ah, Al, Bh, Bl);
}

// ============================ launch ============================
extern "C" void kernel_launch(void* const* d_in, const int* in_sizes, int n_in,
                              void* d_out, int out_size) {
    const float* x  = (const float*)d_in[0];
    const int*   ei = (const int*)d_in[1];
    const float* Wn = (const float*)d_in[2];
    const float* Ws = (const float*)d_in[3];
    float* out = (float*)d_out;
    int N = in_sizes[0] / ROWLEN;
    int E = in_sizes[1] / 2;
    int nblk = (N + 255) / 256;
    int hBlocks = (E + 255) / 256;
    int normBlocks = (N + 7) / 8;
    int gBlocks = (N + 63) / 64;

    void* degPtr = nullptr;
    cudaGetSymbolAddress(&degPtr, g_deg);
    cudaMemsetAsync(degPtr, 0, (size_t)N * sizeof(int));

    hist_wconv_norms_kernel<<<hBlocks + 128 + normBlocks, 256>>>(ei, E, hBlocks, Wn, Ws, x, N);
    scan_part_kernel<<<nblk, 256>>>(N);
    scan_final_kernel<<<nblk, 256>>>(N, nblk);
    scatter_featgemm_kernel<<<hBlocks + gBlocks, 256>>>(ei, E, hBlocks, x, out, N);
    agg_kernel<<<(N + 7) / 8, 256>>>(N);
    gemm_neigh_kernel<<<gBlocks, 256>>>(x, out, N);
}

// round 17
// speedup vs baseline: 1.1515x; 1.1515x over previous
#include <cuda_runtime.h>
#include <cuda_bf16.h>
#include <cstdint>

#define N_MAX 50000
#define E_MAX 640000
#define D 128
#define ROWLEN 129
#define EPSV 1e-9f
#define WMIN 1e-6f

// ---- static scratch ----
__device__ float g_norms[N_MAX];
__device__ int   g_deg[N_MAX];        // zero-initialized at load; re-zeroed by gemm kernel each call
__device__ int   g_cursor[N_MAX];
__device__ int   g_rowptr[N_MAX + 1];
__device__ int   g_col[E_MAX];
__device__ int   g_part[256];
__device__ unsigned short g_Ah[(size_t)N_MAX * 256];
__device__ unsigned short g_Al[(size_t)N_MAX * 256];
__device__ unsigned short g_Bh[128 * 256];
__device__ unsigned short g_Bl[128 * 256];

__device__ __forceinline__ void split_bf16(float v, unsigned short& h, unsigned short& l) {
    __nv_bfloat16 hb = __float2bfloat16(v);
    float lo = v - __bfloat162float(hb);
    h = __bfloat16_as_ushort(hb);
    l = __bfloat16_as_ushort(__float2bfloat16(lo));
}

// ============================ fat kernel 1: hist(1/thread) + wconv + norms ============================
__global__ void hist_wconv_norms_kernel(const int* __restrict__ ei, int E, int hBlocks,
                                        const float* __restrict__ Wn, const float* __restrict__ Ws,
                                        const float* __restrict__ x, int N) {
    int b = blockIdx.x;
    int t = threadIdx.x;
    if (b < hBlocks) {
        int e = b * 256 + t;
        if (e < E) atomicAdd(&g_deg[ei[e]], 1);
    } else if (b < hBlocks + 128) {
        int j = b - hBlocks;
        float v = (t < 128) ? Wn[j * 128 + t] : Ws[j * 128 + (t - 128)];
        split_bf16(v, g_Bh[j * 256 + t], g_Bl[j * 256 + t]);
    } else {
        int row = (b - hBlocks - 128) * 8 + (t >> 5);
        int lane = t & 31;
        if (row >= N) return;
        const float* xr = x + (size_t)row * ROWLEN;
        float a0 = xr[lane], a1 = xr[lane + 32], a2 = xr[lane + 64], a3 = xr[lane + 96];
        float s = a0 * a0 + a1 * a1 + a2 * a2 + a3 * a3;
#pragma unroll
        for (int off = 16; off > 0; off >>= 1) s += __shfl_xor_sync(0xffffffffu, s, off);
        if (lane == 0) g_norms[row] = s + EPSV;
    }
}

// ============================ scan ============================
__global__ void scan_part_kernel(int N) {
    __shared__ int ws[8];
    int t = threadIdx.x, b = blockIdx.x;
    int i = b * 256 + t;
    int v = (i < N) ? g_deg[i] : 0;
#pragma unroll
    for (int off = 16; off > 0; off >>= 1) v += __shfl_xor_sync(0xffffffffu, v, off);
    if ((t & 31) == 0) ws[t >> 5] = v;
    __syncthreads();
    if (t == 0) {
        int s = 0;
#pragma unroll
        for (int w = 0; w < 8; w++) s += ws[w];
        g_part[b] = s;
    }
}

__global__ void scan_final_kernel(int N, int nblk) {
    __shared__ int ws[8];
    __shared__ int boff;
    int t = threadIdx.x, b = blockIdx.x, lane = t & 31, w = t >> 5;

    int pv = (t < b && t < nblk) ? g_part[t] : 0;
#pragma unroll
    for (int off = 16; off > 0; off >>= 1) pv += __shfl_xor_sync(0xffffffffu, pv, off);
    if (lane == 0) ws[w] = pv;
    __syncthreads();
    if (t == 0) {
        int s = 0;
#pragma unroll
        for (int ww = 0; ww < 8; ww++) s += ws[ww];
        boff = s;
    }
    __syncthreads();
    int blockOff = boff;
    __syncthreads();

    int i = b * 256 + t;
    int v = (i < N) ? g_deg[i] : 0;
    int s = v;
#pragma unroll
    for (int off = 1; off < 32; off <<= 1) {
        int u = __shfl_up_sync(0xffffffffu, s, off);
        if (lane >= off) s += u;
    }
    if (lane == 31) ws[w] = s;
    __syncthreads();
    if (w == 0) {
        int p = (lane < 8) ? ws[lane] : 0;
#pragma unroll
        for (int off = 1; off < 8; off <<= 1) {
            int u = __shfl_up_sync(0xffffffffu, p, off);
            if (lane >= off) p += u;
        }
        if (lane < 8) ws[lane] = p;
    }
    __syncthreads();
    int incl = s + (w > 0 ? ws[w - 1] : 0);
    if (i < N) {
        g_rowptr[i + 1] = blockOff + incl;
        g_cursor[i]     = blockOff + incl - v;
    }
    if (b == 0 && t == 0) g_rowptr[0] = 0;
}

// ============================ scatter (1 edge/thread) ============================
__global__ void scatter_kernel(const int* __restrict__ ei, int E) {
    int e = blockIdx.x * blockDim.x + threadIdx.x;
    if (e < E) {
        int r = ei[e];
        int c = ei[E + e];
        int pos = atomicAdd(&g_cursor[r], 1);
        g_col[pos] = c;
    }
}

// ============================ aggregation (R14 shape: coalesced scalar gather + norms table) ============================
__global__ void agg_kernel(const float* __restrict__ x, int N) {
    int warp = (blockIdx.x * blockDim.x + threadIdx.x) >> 5;
    int lane = threadIdx.x & 31;
    if (warp >= N) return;
    int r = warp;
    const float* xr = x + (size_t)r * ROWLEN;
    float xr0 = xr[lane], xr1 = xr[lane + 32], xr2 = xr[lane + 64], xr3 = xr[lane + 96];
    float xrh = xr[128];
    float nr = g_norms[r];

    float acc0 = 0.f, acc1 = 0.f, acc2 = 0.f, acc3 = 0.f, wsum = 0.f;
    int jb = g_rowptr[r], je = g_rowptr[r + 1];
#pragma unroll 2
    for (int j = jb; j < je; j++) {
        int c = g_col[j];
        float nc = g_norms[c];               // warp-uniform, issues early
        const float* xc = x + (size_t)c * ROWLEN;
        float c0 = xc[lane], c1 = xc[lane + 32], c2 = xc[lane + 64], c3 = xc[lane + 96];
        float part = xr0 * c0 + xr1 * c1 + xr2 * c2 + xr3 * c3;
        if (lane == 0) part += xrh * xc[128];
#pragma unroll
        for (int off = 16; off > 0; off >>= 1) part += __shfl_xor_sync(0xffffffffu, part, off);
        float w = __expf(part * part / (nr * nc) - 1.0f);
        acc0 += w * c0; acc1 += w * c1; acc2 += w * c2; acc3 += w * c3;
        wsum += w;
    }
    float inv = 1.0f / fmaxf(wsum, WMIN);
    size_t base = (size_t)r * 256;
    split_bf16(acc0 * inv, g_Ah[base + lane],      g_Al[base + lane]);
    split_bf16(acc1 * inv, g_Ah[base + lane + 32], g_Al[base + lane + 32]);
    split_bf16(acc2 * inv, g_Ah[base + lane + 64], g_Al[base + lane + 64]);
    split_bf16(acc3 * inv, g_Ah[base + lane + 96], g_Al[base + lane + 96]);
    split_bf16(xr0, g_Ah[base + 128 + lane],      g_Al[base + 128 + lane]);
    split_bf16(xr1, g_Ah[base + 128 + lane + 32], g_Al[base + 128 + lane + 32]);
    split_bf16(xr2, g_Ah[base + 128 + lane + 64], g_Al[base + 128 + lane + 64]);
    split_bf16(xr3, g_Ah[base + 128 + lane + 96], g_Al[base + 128 + lane + 96]);
}

// ============================ mma.sync bf16 GEMM + relu + concat (+ deg re-zero) ============================
__device__ __forceinline__ void mma_bf16(float* c, uint32_t a0, uint32_t a1, uint32_t a2, uint32_t a3,
                                         uint32_t b0, uint32_t b1) {
    asm volatile("mma.sync.aligned.m16n8k16.row.col.f32.bf16.bf16.f32 "
                 "{%0,%1,%2,%3}, {%4,%5,%6,%7}, {%8,%9}, {%0,%1,%2,%3};"
                 : "+f"(c[0]), "+f"(c[1]), "+f"(c[2]), "+f"(c[3])
                 : "r"(a0), "r"(a1), "r"(a2), "r"(a3), "r"(b0), "r"(b1));
}

#define KPAD 40

__global__ __launch_bounds__(256) void gemm_mma_kernel(const float* __restrict__ x,
                                                       float* __restrict__ out, int N)
{
    __shared__ unsigned short Ah[64][KPAD], Al[64][KPAD];
    __shared__ unsigned short Bh[128][KPAD], Bl[128][KPAD];
    int t = threadIdx.x, lane = t & 31, wid = t >> 5;
    int row0 = blockIdx.x * 64;
    int wr = (wid & 3) * 16;
    int wc = (wid >> 2) * 64;

    // re-zero g_deg for the next graph replay (replaces host memset launch)
    {
        int i = blockIdx.x * 256 + t;
        if (i < N) g_deg[i] = 0;
    }

    float acc[8][4];
#pragma unroll
    for (int i = 0; i < 8; i++)
#pragma unroll
        for (int j = 0; j < 4; j++) acc[i][j] = 0.f;

    for (int kk = 0; kk < 256; kk += 32) {
#pragma unroll
        for (int it = 0; it < 2; it++) {
            int p = t + it * 256;
            int row = p >> 3, u = p & 7;
            int r = row0 + row;
            uint2 vh = make_uint2(0u, 0u), vl = make_uint2(0u, 0u);
            if (r < N) {
                size_t src = (size_t)r * 256 + kk + u * 4;
                vh = *(const uint2*)(g_Ah + src);
                vl = *(const uint2*)(g_Al + src);
            }
            *(uint2*)&Ah[row][u * 4] = vh;
            *(uint2*)&Al[row][u * 4] = vl;
        }
#pragma unroll
        for (int it = 0; it < 4; it++) {
            int p = t + it * 256;
            int j = p >> 3, u = p & 7;
            size_t src = (size_t)j * 256 + kk + u * 4;
            *(uint2*)&Bh[j][u * 4] = *(const uint2*)(g_Bh + src);
            *(uint2*)&Bl[j][u * 4] = *(const uint2*)(g_Bl + src);
        }
        __syncthreads();
#pragma unroll
        for (int ks = 0; ks < 32; ks += 16) {
            int kq = ks + (lane & 3) * 2;
            int ra = wr + (lane >> 2);
            uint32_t ah0 = *(const uint32_t*)&Ah[ra][kq];
            uint32_t ah1 = *(const uint32_t*)&Ah[ra + 8][kq];
            uint32_t ah2 = *(const uint32_t*)&Ah[ra][kq + 8];
            uint32_t ah3 = *(const uint32_t*)&Ah[ra + 8][kq + 8];
            uint32_t al0 = *(const uint32_t*)&Al[ra][kq];
            uint32_t al1 = *(const uint32_t*)&Al[ra + 8][kq];
            uint32_t al2 = *(const uint32_t*)&Al[ra][kq + 8];
            uint32_t al3 = *(const uint32_t*)&Al[ra + 8][kq + 8];
#pragma unroll
            for (int nt = 0; nt < 8; nt++) {
                int cb = wc + nt * 8 + (lane >> 2);
                uint32_t bh0 = *(const uint32_t*)&Bh[cb][kq];
                uint32_t bh1 = *(const uint32_t*)&Bh[cb][kq + 8];
                uint32_t bl0 = *(const uint32_t*)&Bl[cb][kq];
                uint32_t bl1 = *(const uint32_t*)&Bl[cb][kq + 8];
                mma_bf16(acc[nt], ah0, ah1, ah2, ah3, bh0, bh1);
                mma_bf16(acc[nt], al0, al1, al2, al3, bh0, bh1);
                mma_bf16(acc[nt], ah0, ah1, ah2, ah3, bl0, bl1);
            }
        }
        __syncthreads();
    }

    int r1 = row0 + wr + (lane >> 2);
    int r2 = r1 + 8;
#pragma unroll
    for (int nt = 0; nt < 8; nt++) {
        int col = wc + nt * 8 + (lane & 3) * 2;
        if (r1 < N) {
            float* o = out + (size_t)r1 * ROWLEN + col;
            o[0] = fmaxf(acc[nt][0], 0.f);
            o[1] = fmaxf(acc[nt][1], 0.f);
        }
        if (r2 < N) {
            float* o = out + (size_t)r2 * ROWLEN + col;
            o[0] = fmaxf(acc[nt][2], 0.f);
            o[1] = fmaxf(acc[nt][3], 0.f);
        }
    }
    if (t < 64) {
        int r = row0 + t;
        if (r < N) out[(size_t)r * ROWLEN + 128] = fmaxf(x[(size_t)r * ROWLEN + 128], 0.f);
    }
}

// ============================ launch ============================
extern "C" void kernel_launch(void* const* d_in, const int* in_sizes, int n_in,
                              void* d_out, int out_size) {
    const float* x  = (const float*)d_in[0];
    const int*   ei = (const int*)d_in[1];
    const float* Wn = (const float*)d_in[2];
    const float* Ws = (const float*)d_in[3];
    float* out = (float*)d_out;
    int N = in_sizes[0] / ROWLEN;
    int E = in_sizes[1] / 2;
    int nblk = (N + 255) / 256;
    int hBlocks = (E + 255) / 256;
    int normBlocks = (N + 7) / 8;

    hist_wconv_norms_kernel<<<hBlocks + 128 + normBlocks, 256>>>(ei, E, hBlocks, Wn, Ws, x, N);
    scan_part_kernel<<<nblk, 256>>>(N);
    scan_final_kernel<<<nblk, 256>>>(N, nblk);
    scatter_kernel<<<hBlocks, 256>>>(ei, E);
    agg_kernel<<<(N + 7) / 8, 256>>>(x, N);
    gemm_mma_kernel<<<(N + 63) / 64, 256>>>(x, out, N);
}